// round 12
// baseline (speedup 1.0000x reference)
#include <cuda_runtime.h>
#include <math.h>

// Problem constants (fixed by reference)
#define IMG_W 128
#define IMG_H 128
#define TILE  16              // 16x16 tiles -> 8*8*B = 128 blocks (single wave)
#define PIX   256             // pixels per tile
#define SPLIT 4               // pair-axis interleave in accumulate
#define NT    1024            // threads per block
#define CHUNK 1024            // gaussians per chunk (1 per thread)
#define NWARP (NT / 32)       // 32
#define MAXPAIR (CHUNK / 2 + 1)   // 513 (capacity incl. pad slot)

// ---- packed f32x2 helpers (Blackwell) ----
__device__ __forceinline__ unsigned long long px2(float lo, float hi) {
    unsigned long long d;
    asm("mov.b64 %0, {%1, %2};" : "=l"(d) : "f"(lo), "f"(hi));
    return d;
}
__device__ __forceinline__ void upx2(float& lo, float& hi, unsigned long long v) {
    asm("mov.b64 {%0, %1}, %2;" : "=f"(lo), "=f"(hi) : "l"(v));
}
__device__ __forceinline__ unsigned long long add2(unsigned long long a, unsigned long long b) {
    unsigned long long d;
    asm("add.rn.f32x2 %0, %1, %2;" : "=l"(d) : "l"(a), "l"(b));
    return d;
}
__device__ __forceinline__ unsigned long long mul2(unsigned long long a, unsigned long long b) {
    unsigned long long d;
    asm("mul.rn.f32x2 %0, %1, %2;" : "=l"(d) : "l"(a), "l"(b));
    return d;
}
__device__ __forceinline__ unsigned long long fma2(unsigned long long a, unsigned long long b, unsigned long long c) {
    unsigned long long d;
    asm("fma.rn.f32x2 %0, %1, %2, %3;" : "=l"(d) : "l"(a), "l"(b), "l"(c));
    return d;
}
__device__ __forceinline__ float ex2f(float x) {
    float r;
    asm("ex2.approx.f32 %0, %1;" : "=f"(r) : "f"(x));
    return r;
}

// Fully fused, pipelined, f32x2-packed accumulate.
__global__ void __launch_bounds__(NT)
fused_kernel(float* __restrict__ out,
             const float* __restrict__ pos,
             const float* __restrict__ col,
             const float* __restrict__ opa,
             const float* __restrict__ sca,
             const float* __restrict__ qv,
             const float* __restrict__ tv,
             int N) {
    // Pair-major survivor tables, aliased buffer (also reused for final combine).
    // sA[p] = (-x0,-x1,-y0,-y1)  sB[p] = (K20,K21,lo0,lo1)
    // sC[p] = ( r0, r1, g0, g1)  sD[p] = ( b0, b1)
    __shared__ __align__(16) char smemBuf[MAXPAIR * 16 * 3 + MAXPAIR * 8 + 16];
    __shared__ int sWCnt[NWARP];

    float* Af = (float*)smemBuf;
    float* Bf = Af + MAXPAIR * 4;
    float* Cf = Bf + MAXPAIR * 4;
    float* Df = Cf + MAXPAIR * 4;
    const ulonglong2* uA = (const ulonglong2*)Af;
    const ulonglong2* uB = (const ulonglong2*)Bf;
    const ulonglong2* uC = (const ulonglong2*)Cf;
    const unsigned long long* uD = (const unsigned long long*)Df;

    const int t    = threadIdx.x;
    const int lane = t & 31;
    const int wid  = t >> 5;          // 0..31
    const int sub  = wid >> 3;        // 0..3 : pair-axis slice
    const int pt   = t & (PIX - 1);   // pixel 0..255
    const int b    = blockIdx.z;
    const int x0   = blockIdx.x * TILE;
    const int y0   = blockIdx.y * TILE;
    const float xf = (float)(x0 + (pt & (TILE - 1)));
    const float yf = (float)(y0 + (pt >> 4));
    const unsigned long long xfp = px2(xf, xf);
    const unsigned long long yfp = px2(yf, yf);

    const float fx0 = (float)x0, fx1 = (float)(x0 + TILE - 1);
    const float fy0 = (float)y0, fy1 = (float)(y0 + TILE - 1);

    // Camera for this batch (broadcast loads; every thread computes the same R).
    float qw = qv[b * 4 + 0], qx = qv[b * 4 + 1], qy = qv[b * 4 + 2], qz = qv[b * 4 + 3];
    float inv = rsqrtf(qw * qw + qx * qx + qy * qy + qz * qz);
    qw *= inv; qx *= inv; qy *= inv; qz *= inv;
    const float R00 = 1.f - 2.f * (qy * qy + qz * qz), R01 = 2.f * (qx * qy - qz * qw), R02 = 2.f * (qx * qz + qy * qw);
    const float R10 = 2.f * (qx * qy + qz * qw), R11 = 1.f - 2.f * (qx * qx + qz * qz), R12 = 2.f * (qy * qz - qx * qw);
    const float R20 = 2.f * (qx * qz - qy * qw), R21 = 2.f * (qy * qz + qx * qw), R22 = 1.f - 2.f * (qx * qx + qy * qy);
    const float tx = tv[b * 3 + 0], ty = tv[b * 3 + 1], tz = tv[b * 3 + 2];

    unsigned long long accD2 = 0ull, accR2 = 0ull, accG2 = 0ull, accB2 = 0ull;

    // ---- Prologue: load chunk 0 inputs ----
    float cPx = 0.f, cPy = 0.f, cPz = 0.f, cSc = 1.f, cOp = 1e-30f;
    float cCr = 0.f, cCg = 0.f, cCb = 0.f;
    if (t < N) {
        cPx = pos[t * 3 + 0]; cPy = pos[t * 3 + 1]; cPz = pos[t * 3 + 2];
        cSc = sca[t]; cOp = opa[t];
        cCr = col[t * 3 + 0]; cCg = col[t * 3 + 1]; cCb = col[t * 3 + 2];
    }

    for (int base = 0; base < N; base += CHUNK) {
        const bool valid = (base + t) < N;

        // ---- Phase 1: project + cull (tight bound incl. log2 op) ----
        float czm = R20 * cPx + R21 * cPy + R22 * cPz + tz;
        float iz  = __fdividef(1.0f, czm);
        float projx = fmaf((R00 * cPx + R01 * cPy + R02 * cPz + tx) * iz, 500.0f, 64.0f);
        float projy = fmaf((R10 * cPx + R11 * cPy + R12 * cPz + ty) * iz, 500.0f, 64.0f);
        float K2 = __fdividef(-0.72134752044f, cSc * cSc);   // -1/(2 var ln2)
        float lo = log2f(fmaxf(cOp, 1e-30f));

        float dx = fmaxf(0.f, fmaxf(fx0 - projx, projx - fx1));
        float dy = fmaxf(0.f, fmaxf(fy0 - projy, projy - fy1));
        float amax = fmaf(K2, fmaf(dx, dx, dy * dy), lo);
        bool keepIt = valid && (amax > -60.f);               // NaN fails -> culled
        float svCr = cCr, svCg = cCg, svCb = cCb;

        // ---- Prefetch next chunk (drains behind compaction + accumulate) ----
        {
            int g = base + CHUNK + t;
            if (g < N) {
                cPx = pos[g * 3 + 0]; cPy = pos[g * 3 + 1]; cPz = pos[g * 3 + 2];
                cSc = sca[g]; cOp = opa[g];
                cCr = col[g * 3 + 0]; cCg = col[g * 3 + 1]; cCb = col[g * 3 + 2];
            }
        }

        // ---- Phase 2: ballot; counts to shared; barrier doubles as reuse guard ----
        unsigned m = __ballot_sync(0xffffffffu, keepIt);
        int myOff = __popc(m & ((1u << lane) - 1u));
        if (lane == 0) sWCnt[wid] = __popc(m);
        __syncthreads();

        // ---- Phase 3: every warp scans the 32 counts; survivors stored paired ----
        int cvec = sWCnt[lane];
        int incl = cvec;
        #pragma unroll
        for (int o = 1; o < 32; o <<= 1) {
            int v = __shfl_up_sync(0xffffffffu, incl, o);
            if (lane >= o) incl += v;
        }
        int warpBase = __shfl_sync(0xffffffffu, incl - cvec, wid);
        int cnt      = __shfl_sync(0xffffffffu, incl, 31);

        if (keepIt) {
            int i = warpBase + myOff;
            int p4 = (i >> 1) * 4;
            int h  = i & 1;
            Af[p4 + h]     = -projx;
            Af[p4 + 2 + h] = -projy;
            Bf[p4 + h]     = K2;
            Bf[p4 + 2 + h] = lo;
            Cf[p4 + h]     = svCr;
            Cf[p4 + 2 + h] = svCg;
            Df[(i >> 1) * 2 + h] = svCb;
        }
        if (t == 0 && (cnt & 1)) {       // pad slot: e = 2^-10000 = 0
            int p4 = (cnt >> 1) * 4;
            Af[p4 + 1] = 0.f; Af[p4 + 3] = 0.f;
            Bf[p4 + 1] = 0.f; Bf[p4 + 3] = -10000.f;
            Cf[p4 + 1] = 0.f; Cf[p4 + 3] = 0.f;
            Df[(cnt >> 1) * 2 + 1] = 0.f;
        }
        __syncthreads();

        // ---- Phase 4: packed accumulate over survivor pairs, SPLIT-strided ----
        const int cntP = (cnt + 1) >> 1;
        #pragma unroll 2
        for (int p = sub; p < cntP; p += SPLIT) {
            ulonglong2 av = uA[p];               // (-x pair, -y pair)
            ulonglong2 bv = uB[p];               // (K2 pair, lo pair)
            ulonglong2 cv = uC[p];               // (r pair, g pair)
            unsigned long long bp = uD[p];       // (b pair)
            unsigned long long dxp = add2(xfp, av.x);
            unsigned long long dyp = add2(yfp, av.y);
            unsigned long long d2p = fma2(dxp, dxp, mul2(dyp, dyp));
            unsigned long long argp = fma2(bv.x, d2p, bv.y);
            float a0, a1; upx2(a0, a1, argp);
            unsigned long long ep = px2(ex2f(a0), ex2f(a1));
            accD2 = add2(accD2, ep);
            accR2 = fma2(ep, cv.x, accR2);
            accG2 = fma2(ep, cv.y, accG2);
            accB2 = fma2(ep, bp,   accB2);
        }
        // no trailing sync: next iteration's post-ballot barrier guards reuse
    }

    // ---- Final: unpack (fixed order), 4-sub combine via reused shared ----
    __syncthreads();
    float4* sAcc = (float4*)smemBuf;
    {
        float l0, h0, l1, h1, l2, h2, l3, h3;
        upx2(l0, h0, accR2); upx2(l1, h1, accG2);
        upx2(l2, h2, accB2); upx2(l3, h3, accD2);
        sAcc[t] = make_float4(l0 + h0, l1 + h1, l2 + h2, l3 + h3);
    }
    __syncthreads();

    if (t < PIX) {
        float4 a0 = sAcc[t];
        float4 a1 = sAcc[t + PIX];
        float4 a2 = sAcc[t + 2 * PIX];
        float4 a3 = sAcc[t + 3 * PIX];
        float r  = (a0.x + a1.x) + (a2.x + a3.x);
        float g  = (a0.y + a1.y) + (a2.y + a3.y);
        float bl = (a0.z + a1.z) + (a2.z + a3.z);
        float d  = (a0.w + a1.w) + (a2.w + a3.w);
        float invd = 1.0f / (d + 1e-8f);
        int px = x0 + (t & (TILE - 1));
        int py = y0 + (t >> 4);
        int o = ((b * 3 + 0) * IMG_H + py) * IMG_W + px;
        out[o]                     = r  * invd;
        out[o + IMG_H * IMG_W]     = g  * invd;
        out[o + 2 * IMG_H * IMG_W] = bl * invd;
    }
}

extern "C" void kernel_launch(void* const* d_in, const int* in_sizes, int n_in,
                              void* d_out, int out_size) {
    const float* positions = (const float*)d_in[0];  // (N,3)
    const float* colors    = (const float*)d_in[1];  // (N,3)
    const float* opacities = (const float*)d_in[2];  // (N,1)
    const float* scales    = (const float*)d_in[3];  // (N,1)
    const float* qvec      = (const float*)d_in[4];  // (B,4)
    const float* tvec      = (const float*)d_in[5];  // (B,3)

    int N = in_sizes[0] / 3;
    int B = in_sizes[4] / 4;

    dim3 grid(IMG_W / TILE, IMG_H / TILE, B);
    fused_kernel<<<grid, NT>>>((float*)d_out, positions, colors, opacities,
                               scales, qvec, tvec, N);
}